// round 13
// baseline (speedup 1.0000x reference)
#include <cuda_runtime.h>

#define B   32
#define HH  512
#define NN  (512*512)          // 262144 per row
#define K1  180
#define K2  360
#define NTASK 96               // 3 arrays x 32 rows
#define THRESH_F 2.75f
#define KEYB16  0xC030u        // orderKey(2.75f) >> 16
#define CAP  4096
#define SCAP 2048
#define TCAP 512
#define CH   32                // units per task
#define CHUNKF (NN/CH)         // 8192 floats per unit
#define NUNITS (NTASK*CH)      // 3072
#define CGRID  1184            // 8 blocks/SM-capacity, ticket-scheduled
#define FULLM  0xffffffffu

__device__ int                 g_candCount[NTASK];
__device__ unsigned long long  g_cand[NTASK][CAP];
__device__ int                 g_topk[NTASK][K2];
__device__ float               g_loss[B];
__device__ int                 g_rowDone[B];
__device__ int                 g_done;
__device__ int                 g_ticket;

__device__ __forceinline__ unsigned orderKey(float f) {
    unsigned u = __float_as_uint(f);
    return u ^ (((unsigned)((int)u >> 31)) | 0x80000000u);
}

// ---------------------------------------------------------------------------
// 1) Collect: ticket-scheduled units. Pass A vote-free compare -> 32-bit mask;
//    Pass B: ONE atomic per warp per unit (scan-based), then drain.
// ---------------------------------------------------------------------------
__global__ void __launch_bounds__(256, 6) collectKernel(
        const float* __restrict__ rv,
        const float* __restrict__ ri,
        const float* __restrict__ rf) {
    __shared__ int s_unit;
    int t = threadIdx.x;
    int lane = t & 31;

    for (;;) {
        if (t == 0) s_unit = atomicAdd(&g_ticket, 1);
        __syncthreads();
        int unit = s_unit;
        if (unit >= NUNITS) break;

        int task  = unit >> 5;             // 0..95
        int chunk = unit & 31;
        int a = task >> 5, row = task & 31;
        const float* srcf = (a == 0 ? rv : (a == 1 ? ri : rf))
                            + (size_t)row * NN + (size_t)chunk * CHUNKF;
        const float4* p = (const float4*)srcf;
        unsigned idxBase = (unsigned)chunk * CHUNKF;

        // ---- Pass A: 8 float4 per thread, compare-only ----
        float4 v[8];
        #pragma unroll
        for (int q = 0; q < 8; q++) v[q] = p[t + q * 256];
        unsigned mask = 0u;
        #pragma unroll
        for (int q = 0; q < 8; q++) {
            unsigned bits = (unsigned)(v[q].x >= THRESH_F)
                          | ((unsigned)(v[q].y >= THRESH_F) << 1)
                          | ((unsigned)(v[q].z >= THRESH_F) << 2)
                          | ((unsigned)(v[q].w >= THRESH_F) << 3);
            mask |= bits << (q * 4);
        }

        // ---- Pass B: single warp atomic via inclusive scan ----
        int cnt = __popc(mask);
        int inc = cnt;
        #pragma unroll
        for (int d = 1; d < 32; d <<= 1) {
            int n = __shfl_up_sync(FULLM, inc, d);
            if (lane >= d) inc += n;
        }
        int tot = __shfl_sync(FULLM, inc, 31);
        if (tot) {
            int base0 = 0;
            if (lane == 0) base0 = atomicAdd(&g_candCount[task], tot);
            base0 = __shfl_sync(FULLM, base0, 0);
            int pos = base0 + inc - cnt;
            unsigned m = mask;
            while (m) {
                int bpos = __ffs(m) - 1; m &= m - 1u;
                int slot = bpos >> 2, c = bpos & 3;
                int eoff = (t + slot * 256) * 4 + c;
                float f = srcf[eoff];                   // L1-resident reload
                unsigned gi = idxBase + (unsigned)eoff;
                if (pos < CAP)
                    g_cand[task][pos] =
                        ((unsigned long long)orderKey(f) << 32) | (unsigned)(~gi);
                pos++;
            }
        }
        __syncthreads();    // protect s_unit before next ticket
    }
}

// ---------------------------------------------------------------------------
// 2) Fused select (per task) + coverage (last task of each row) + finalize
// ---------------------------------------------------------------------------
__global__ void __launch_bounds__(512) selectCoverageKernel(
        const float* __restrict__ rv,
        const float* __restrict__ ri,
        const float* __restrict__ rf,
        float* __restrict__ out) {
    __shared__ union SM {
        struct { unsigned long long sc[SCAP]; unsigned long long s2[TCAP];
                 unsigned hist[1024]; } sel;                       // 24 KB
        unsigned bitmap[NN / 32];                                  // 32 KB
    } sm;
    __shared__ int s_n, s_m, s_flag, s_cover, s_denom;
    __shared__ unsigned s_binLo;
    __shared__ int s_rv[K1];

    int task = blockIdx.x, t = threadIdx.x;
    int need = (task < 2 * B) ? K1 : K2;
    int row = task & 31;
    int cnt = g_candCount[task];
    if (t == 0) { s_n = 0; s_m = 0; }
    for (int i = t; i < 1024; i += 512) sm.sel.hist[i] = 0;
    __syncthreads();

    // ---------------- Select ----------------
    const unsigned long long* rankSrc;
    int n2;
    if (cnt >= need && cnt <= SCAP) {
        for (int i = t; i < cnt; i += 512) {
            unsigned long long v = g_cand[task][i];
            sm.sel.sc[i] = v;
            unsigned bin = min((unsigned)(v >> 48) - KEYB16, 1023u);
            atomicAdd(&sm.sel.hist[bin], 1u);
        }
        __syncthreads();
        if (t == 0) {
            unsigned pre = 0; unsigned binLo = 0;
            for (int i = 0; i < 1024; i++) {
                if (cnt - (int)(pre + sm.sel.hist[i]) < need) { binLo = i; break; }
                pre += sm.sel.hist[i];
            }
            s_binLo = binLo;
        }
        __syncthreads();
        unsigned binLo = s_binLo;
        for (int i = t; i < cnt; i += 512) {
            unsigned long long v = sm.sel.sc[i];
            unsigned bin = min((unsigned)(v >> 48) - KEYB16, 1023u);
            if (bin >= binLo) {
                int pos = atomicAdd(&s_m, 1);
                if (pos < TCAP) sm.sel.s2[pos] = v;
            }
        }
        __syncthreads();
        if (s_m <= TCAP) { rankSrc = sm.sel.s2; n2 = s_m; }
        else             { rankSrc = sm.sel.sc; n2 = cnt; }
    } else {
        // exact fallback: radix-hist rescan of this task's row
        int a = task >> 5;
        const float* src = (a == 0 ? rv : (a == 1 ? ri : rf)) + (size_t)row * NN;
        for (int i = t; i < NN; i += 512)
            atomicAdd(&sm.sel.hist[orderKey(src[i]) >> 22], 1u);
        __syncthreads();
        if (t == 0) {
            unsigned acc = 0; unsigned bi = 0;
            for (int i = 1023; i >= 0; i--) {
                acc += sm.sel.hist[i];
                if (acc >= (unsigned)need) { bi = i; break; }
            }
            s_binLo = bi << 22;
        }
        __syncthreads();
        unsigned binLo = s_binLo;
        for (int i = t; i < NN; i += 512) {
            unsigned k = orderKey(src[i]);
            if (k >= binLo) {
                int pos = atomicAdd(&s_n, 1);
                if (pos < SCAP)
                    sm.sel.sc[pos] = ((unsigned long long)k << 32) |
                                     (unsigned)(~(unsigned)i);
            }
        }
        __syncthreads();
        rankSrc = sm.sel.sc; n2 = min(s_n, SCAP);
    }

    for (int i = t; i < n2; i += 512) {
        unsigned long long me = rankSrc[i];
        int r = 0;
        #pragma unroll 8
        for (int j = 0; j < n2; j++) r += (rankSrc[j] > me);
        if (r < need) g_topk[task][r] = (int)(~(unsigned)me);
    }

    __threadfence();
    __syncthreads();
    if (t == 0) s_flag = (atomicAdd(&g_rowDone[row], 1) == 2) ? 1 : 0;
    __syncthreads();
    if (!s_flag) return;
    __threadfence();   // acquire topk writes from sibling tasks

    // ---------------- Coverage for this row ----------------
    {
        int b = row;
        for (int i = t; i < NN / 32; i += 512) sm.bitmap[i] = 0;
        if (t == 0) { s_cover = 0; s_denom = 0; }
        for (int i = t; i < K1; i += 512) s_rv[i] = g_topk[0 * B + b][i];
        __syncthreads();

        if (t < K2) {
            int idx = g_topk[2 * B + b][t];
            int y = idx >> 9, x = idx & 511;
            int lo = max(x - 3, 0), hi = min(x + 3, 511);
            #pragma unroll
            for (int dy = -3; dy <= 3; dy++) {
                int yy = y + dy;
                if (yy < 0 || yy >= HH) continue;
                int wbase = yy << 4;
                int w0 = lo >> 5, w1 = hi >> 5;
                if (w0 == w1) {
                    unsigned msk = ((1u << (hi - lo + 1)) - 1u) << (lo & 31);
                    atomicOr(&sm.bitmap[wbase + w0], msk);
                } else {
                    atomicOr(&sm.bitmap[wbase + w0], 0xFFFFFFFFu << (lo & 31));
                    atomicOr(&sm.bitmap[wbase + w1], (1u << ((hi & 31) + 1)) - 1u);
                }
            }
        }
        __syncthreads();

        if (t < K2) {
            int idx; bool isSrc;
            if (t < K1) { idx = s_rv[t]; isSrc = true; }
            else {
                idx = g_topk[1 * B + b][t - K1];
                isSrc = true;
                for (int j = 0; j < K1; j++)
                    if (s_rv[j] == idx) { isSrc = false; break; }
            }
            if (isSrc) {
                atomicAdd(&s_denom, 1);
                if ((sm.bitmap[idx >> 5] >> (idx & 31)) & 1u) atomicAdd(&s_cover, 1);
            }
        }
        __syncthreads();
        if (t == 0) {
            g_loss[b] = 1.0f - (float)s_cover / (float)max(s_denom, 1);
            __threadfence();
            s_flag = (atomicAdd(&g_done, 1) == B - 1) ? 1 : 0;
        }
        __syncthreads();
    }
    if (!s_flag) return;

    // ---------------- Finalize + reset scratch for graph replay ----------------
    if (t == 0) {
        __threadfence();
        volatile float* gl = g_loss;
        float s = 0.0f;
        for (int i = 0; i < B; i++) s += gl[i];
        out[0] = s / (float)B;
        g_done = 0;
        g_ticket = 0;
    }
    if (t < NTASK) g_candCount[t] = 0;
    if (t < B)     g_rowDone[t] = 0;
}

extern "C" void kernel_launch(void* const* d_in, const int* in_sizes, int n_in,
                              void* d_out, int out_size) {
    const float* rv = (const float*)d_in[0];
    const float* ri = (const float*)d_in[1];
    const float* rf = (const float*)d_in[2];

    collectKernel<<<CGRID, 256>>>(rv, ri, rf);
    selectCoverageKernel<<<NTASK, 512>>>(rv, ri, rf, (float*)d_out);
}

// round 16
// speedup vs baseline: 1.0557x; 1.0557x over previous
#include <cuda_runtime.h>

#define B   32
#define HH  512
#define NN  (512*512)          // 262144 per row
#define K1  180
#define K2  360
#define NTASK 96               // 3 arrays x 32 rows
#define THRESH_F 2.75f
#define KEYB16  0xC030u        // orderKey(2.75f) >> 16
#define CAP  4096
#define SCAP 2048
#define TCAP 512
#define CH   32                // units per task
#define CHUNKF (NN/CH)         // 8192 floats per unit
#define NUNITS (NTASK*CH)      // 3072
#define CGRID  1184
#define FULLM  0xffffffffu

__device__ int                 g_candCount[NTASK];
__device__ unsigned long long  g_cand[NTASK][CAP];
__device__ int                 g_topk[NTASK][K2];
__device__ float               g_loss[B];
__device__ int                 g_done;
__device__ int                 g_ticket;

__device__ __forceinline__ unsigned orderKey(float f) {
    unsigned u = __float_as_uint(f);
    return u ^ (((unsigned)((int)u >> 31)) | 0x80000000u);
}

// ---------------------------------------------------------------------------
// 1) Collect: ticket-scheduled units. Pass A vote-free compare -> 32-bit mask;
//    Pass B: ONE atomic per warp per unit (scan-based), then drain.
//    (Measured ~18.5us in R13 — unchanged.)
// ---------------------------------------------------------------------------
__global__ void __launch_bounds__(256, 6) collectKernel(
        const float* __restrict__ rv,
        const float* __restrict__ ri,
        const float* __restrict__ rf) {
    __shared__ int s_unit;
    int t = threadIdx.x;
    int lane = t & 31;

    for (;;) {
        if (t == 0) s_unit = atomicAdd(&g_ticket, 1);
        __syncthreads();
        int unit = s_unit;
        if (unit >= NUNITS) break;

        int task  = unit >> 5;             // 0..95
        int chunk = unit & 31;
        int a = task >> 5, row = task & 31;
        const float* srcf = (a == 0 ? rv : (a == 1 ? ri : rf))
                            + (size_t)row * NN + (size_t)chunk * CHUNKF;
        const float4* p = (const float4*)srcf;
        unsigned idxBase = (unsigned)chunk * CHUNKF;

        // ---- Pass A: 8 float4 per thread, compare-only ----
        float4 v[8];
        #pragma unroll
        for (int q = 0; q < 8; q++) v[q] = p[t + q * 256];
        unsigned mask = 0u;
        #pragma unroll
        for (int q = 0; q < 8; q++) {
            unsigned bits = (unsigned)(v[q].x >= THRESH_F)
                          | ((unsigned)(v[q].y >= THRESH_F) << 1)
                          | ((unsigned)(v[q].z >= THRESH_F) << 2)
                          | ((unsigned)(v[q].w >= THRESH_F) << 3);
            mask |= bits << (q * 4);
        }

        // ---- Pass B: single warp atomic via inclusive scan ----
        int cnt = __popc(mask);
        int inc = cnt;
        #pragma unroll
        for (int d = 1; d < 32; d <<= 1) {
            int n = __shfl_up_sync(FULLM, inc, d);
            if (lane >= d) inc += n;
        }
        int tot = __shfl_sync(FULLM, inc, 31);
        if (tot) {
            int base0 = 0;
            if (lane == 0) base0 = atomicAdd(&g_candCount[task], tot);
            base0 = __shfl_sync(FULLM, base0, 0);
            int pos = base0 + inc - cnt;
            unsigned m = mask;
            while (m) {
                int bpos = __ffs(m) - 1; m &= m - 1u;
                int slot = bpos >> 2, c = bpos & 3;
                int eoff = (t + slot * 256) * 4 + c;
                float f = srcf[eoff];                   // L1-resident reload
                unsigned gi = idxBase + (unsigned)eoff;
                if (pos < CAP)
                    g_cand[task][pos] =
                        ((unsigned long long)orderKey(f) << 32) | (unsigned)(~gi);
                pos++;
            }
        }
        __syncthreads();    // protect s_unit before next ticket
    }
}

// ---------------------------------------------------------------------------
// 2) Exact top-k per task: fine-hist trim, then rank trimmed survivors.
//    (R10 structure — measured fast as a separate kernel.)
// ---------------------------------------------------------------------------
__global__ void __launch_bounds__(512) selectKernel(
        const float* __restrict__ rv,
        const float* __restrict__ ri,
        const float* __restrict__ rf) {
    __shared__ unsigned long long sc[SCAP];
    __shared__ unsigned long long s2[TCAP];
    __shared__ unsigned sh[1024];
    __shared__ int s_n, s_m;
    __shared__ unsigned s_binLo;

    int task = blockIdx.x, t = threadIdx.x;
    int need = (task < 2 * B) ? K1 : K2;
    int cnt = g_candCount[task];
    if (t == 0) { s_n = 0; s_m = 0; }
    for (int i = t; i < 1024; i += 512) sh[i] = 0;
    __syncthreads();

    const unsigned long long* rankSrc;
    int n2;
    if (cnt >= need && cnt <= SCAP) {
        for (int i = t; i < cnt; i += 512) {
            unsigned long long v = g_cand[task][i];
            sc[i] = v;
            unsigned bin = min((unsigned)(v >> 48) - KEYB16, 1023u);
            atomicAdd(&sh[bin], 1u);
        }
        __syncthreads();
        if (t == 0) {
            unsigned pre = 0; unsigned binLo = 0;
            for (int i = 0; i < 1024; i++) {
                if (cnt - (int)(pre + sh[i]) < need) { binLo = i; break; }
                pre += sh[i];
            }
            s_binLo = binLo;
        }
        __syncthreads();
        unsigned binLo = s_binLo;
        for (int i = t; i < cnt; i += 512) {
            unsigned long long v = sc[i];
            unsigned bin = min((unsigned)(v >> 48) - KEYB16, 1023u);
            if (bin >= binLo) {
                int pos = atomicAdd(&s_m, 1);
                if (pos < TCAP) s2[pos] = v;
            }
        }
        __syncthreads();
        if (s_m <= TCAP) { rankSrc = s2; n2 = s_m; }
        else             { rankSrc = sc; n2 = cnt; }
    } else {
        // exact fallback: radix-hist rescan of this task's row
        int a = task >> 5, row = task & 31;
        const float* src = (a == 0 ? rv : (a == 1 ? ri : rf)) + (size_t)row * NN;
        for (int i = t; i < NN; i += 512)
            atomicAdd(&sh[orderKey(src[i]) >> 22], 1u);
        __syncthreads();
        if (t == 0) {
            unsigned acc = 0; unsigned bi = 0;
            for (int i = 1023; i >= 0; i--) {
                acc += sh[i];
                if (acc >= (unsigned)need) { bi = i; break; }
            }
            s_binLo = bi << 22;
        }
        __syncthreads();
        unsigned binLo = s_binLo;
        for (int i = t; i < NN; i += 512) {
            unsigned k = orderKey(src[i]);
            if (k >= binLo) {
                int pos = atomicAdd(&s_n, 1);
                if (pos < SCAP)
                    sc[pos] = ((unsigned long long)k << 32) | (unsigned)(~(unsigned)i);
            }
        }
        __syncthreads();
        rankSrc = sc; n2 = min(s_n, SCAP);
    }

    for (int i = t; i < n2; i += 512) {
        unsigned long long me = rankSrc[i];
        int r = 0;
        #pragma unroll 8
        for (int j = 0; j < n2; j++) r += (rankSrc[j] > me);
        if (r < need) g_topk[task][r] = (int)(~(unsigned)me);
    }
}

// ---------------------------------------------------------------------------
// 3) Coverage via dilated rf bitmap; last block finalizes + resets scratch
// ---------------------------------------------------------------------------
__global__ void __launch_bounds__(512) coverageKernel(float* __restrict__ out) {
    __shared__ unsigned bitmap[NN / 32];
    __shared__ int s_rv[K1];
    __shared__ int s_cover, s_denom;
    __shared__ bool s_isLast;

    int b = blockIdx.x, t = threadIdx.x;
    for (int i = t; i < NN / 32; i += blockDim.x) bitmap[i] = 0;
    if (t == 0) { s_cover = 0; s_denom = 0; }
    for (int i = t; i < K1; i += blockDim.x) s_rv[i] = g_topk[0 * B + b][i];
    __syncthreads();

    if (t < K2) {
        int idx = g_topk[2 * B + b][t];
        int y = idx >> 9, x = idx & 511;
        int lo = max(x - 3, 0), hi = min(x + 3, 511);
        #pragma unroll
        for (int dy = -3; dy <= 3; dy++) {
            int yy = y + dy;
            if (yy < 0 || yy >= HH) continue;
            int wbase = yy << 4;
            int w0 = lo >> 5, w1 = hi >> 5;
            if (w0 == w1) {
                unsigned msk = ((1u << (hi - lo + 1)) - 1u) << (lo & 31);
                atomicOr(&bitmap[wbase + w0], msk);
            } else {
                atomicOr(&bitmap[wbase + w0], 0xFFFFFFFFu << (lo & 31));
                atomicOr(&bitmap[wbase + w1], (1u << ((hi & 31) + 1)) - 1u);
            }
        }
    }
    __syncthreads();

    if (t < K2) {
        int idx; bool isSrc;
        if (t < K1) { idx = s_rv[t]; isSrc = true; }
        else {
            idx = g_topk[1 * B + b][t - K1];
            isSrc = true;
            for (int j = 0; j < K1; j++)
                if (s_rv[j] == idx) { isSrc = false; break; }
        }
        if (isSrc) {
            atomicAdd(&s_denom, 1);
            if ((bitmap[idx >> 5] >> (idx & 31)) & 1u) atomicAdd(&s_cover, 1);
        }
    }
    __syncthreads();
    if (t == 0) {
        g_loss[b] = 1.0f - (float)s_cover / (float)max(s_denom, 1);
        __threadfence();
        s_isLast = (atomicAdd(&g_done, 1) == B - 1);
    }
    __syncthreads();

    if (s_isLast) {
        if (t == 0) {
            volatile float* gl = g_loss;
            float s = 0.0f;
            for (int i = 0; i < B; i++) s += gl[i];
            out[0] = s / (float)B;
            g_done = 0;
            g_ticket = 0;                  // collect uses ticket each replay
        }
        if (t < NTASK) g_candCount[t] = 0;
    }
}

extern "C" void kernel_launch(void* const* d_in, const int* in_sizes, int n_in,
                              void* d_out, int out_size) {
    const float* rv = (const float*)d_in[0];
    const float* ri = (const float*)d_in[1];
    const float* rf = (const float*)d_in[2];

    collectKernel<<<CGRID, 256>>>(rv, ri, rf);
    selectKernel<<<NTASK, 512>>>(rv, ri, rf);
    coverageKernel<<<B, 512>>>((float*)d_out);
}